// round 9
// baseline (speedup 1.0000x reference)
#include <cuda_runtime.h>
#include <math.h>

#define NB    8192
#define GRID  32
#define NT    1024
#define RPB   256          // rows per block = chunk size
#define CHK   256
#define TPAD  257          // padded chunk stride in smem floats

__device__ __align__(16) float g_tsrt[NB];
__device__ __align__(16) float g_pe[NB];
__device__ float g_nll[GRID];
__device__ float g_per[GRID];
__device__ int   g_cnt[GRID];
__device__ int   g_ticket;
__device__ unsigned g_bcount;
__device__ volatile unsigned g_bgen;

#define BAR256() asm volatile("bar.sync 1, 256;" ::: "memory")

__device__ __forceinline__ void grid_bar() {
    __threadfence();            // release
    __syncthreads();
    if (threadIdx.x == 0) {
        unsigned gen = g_bgen;
        if (atomicAdd(&g_bcount, 1u) == GRID - 1) {
            g_bcount = 0;
            __threadfence();
            g_bgen = gen + 1;
        } else {
            while (g_bgen == gen) { __nanosleep(32); }
        }
        __threadfence();        // acquire
    }
    __syncthreads();
}

// in-register compare-exchange, positions a<b, payload follows key
#define CEP(A,B,D) { bool sw = (D) ? (kt[A] < kt[B]) : (kt[A] > kt[B]); \
    if (sw) { float tk_=kt[A];kt[A]=kt[B];kt[B]=tk_; \
              float te_=ke[A];ke[A]=ke[B];ke[B]=te_; } }

extern "C" __global__ void __launch_bounds__(NT, 1)
surv_one_kernel(const float* __restrict__ outputs,
                const int* __restrict__ y,
                const float* __restrict__ t,
                const int* __restrict__ c,
                float* __restrict__ out)
{
    __shared__ __align__(16) float se[RPB];      // e per local row (orig order)
    __shared__ __align__(16) float srisk[RPB];
    __shared__ __align__(16) float st[RPB];      // original t per local row
    __shared__ int   sc[RPB];
    __shared__ __align__(16) float t_tab[32 * TPAD];
    __shared__ float wpart[8];
    __shared__ float bredf[32];
    __shared__ int   bredi[32];
    __shared__ int   is_last;

    const int tid  = threadIdx.x;
    const int blk  = blockIdx.x;
    const int lane = tid & 31;
    const int wid  = tid >> 5;

    // ================= Phase A: first 8 warps, 1 row/thread =================
    if (tid < RPB) {
        const int r = blk * RPB + tid;
        float4 o4 = ((const float4*)outputs)[r];
        float a0 = __expf(o4.x), a1 = __expf(o4.y);
        float a2 = __expf(o4.z), a3 = __expf(o4.w);
        // tails for Sum(S_k) = Q / P3, heads for NLL
        float v3   = 1.f + a3;
        float v23  = (1.f + a2) * v3;
        float v123 = (1.f + a1) * v23;
        float Q    = v123 + v23 + v3 + 1.f;
        float h0 = 1.f + a0;
        float h1 = h0 * (1.f + a1);
        float h2 = h1 * (1.f + a2);
        float h3 = h0 * v123;                 // P3
        float risk = -__fdividef(Q, h3);

        int yi = y[r];
        float Py = (yi == 0) ? h0 : (yi == 1) ? h1 : (yi == 2) ? h2 : h3;
        float oy = (yi == 0) ? o4.x : (yi == 1) ? o4.y : (yi == 2) ? o4.z : o4.w;
        float cf = (float)c[r];
        float nll = __logf(Py) - (1.f - cf) * oy;   // exact NLL collapse

        se[tid]    = __expf(risk);
        srisk[tid] = risk;
        sc[tid]    = c[r];
        st[tid]    = t[r];

        #pragma unroll
        for (int off = 16; off > 0; off >>= 1)
            nll += __shfl_xor_sync(0xffffffffu, nll, off);
        if (lane == 0) wpart[wid] = nll;
        BAR256();                      // se/st/sc/srisk + wpart visible to warps 0-7
        if (tid == 0) {
            float s = 0.f;
            #pragma unroll
            for (int w = 0; w < 8; w++) s += wpart[w];
            g_nll[blk] = s;
        }
    }

    // ================= Phase B: warp 0 register bitonic (256, 8/lane) =========
    if (wid == 0) {
        float kt[8], ke[8];
        {
            float4 a = ((const float4*)st)[lane * 2];
            float4 b = ((const float4*)st)[lane * 2 + 1];
            kt[0]=a.x; kt[1]=a.y; kt[2]=a.z; kt[3]=a.w;
            kt[4]=b.x; kt[5]=b.y; kt[6]=b.z; kt[7]=b.w;
            float4 p = ((const float4*)se)[lane * 2];
            float4 q = ((const float4*)se)[lane * 2 + 1];
            ke[0]=p.x; ke[1]=p.y; ke[2]=p.z; ke[3]=p.w;
            ke[4]=q.x; ke[5]=q.y; ke[6]=q.z; ke[7]=q.w;
        }
        // element index x = 8*lane + i; sort DESCENDING by t
        // k=2
        CEP(0,1,true); CEP(2,3,false); CEP(4,5,true); CEP(6,7,false);
        // k=4
        CEP(0,2,true);  CEP(1,3,true);  CEP(4,6,false); CEP(5,7,false);
        CEP(0,1,true);  CEP(2,3,true);  CEP(4,5,false); CEP(6,7,false);
        // k=8: desc depends on lane parity
        {
            bool d = ((lane & 1) == 0);
            CEP(0,4,d); CEP(1,5,d); CEP(2,6,d); CEP(3,7,d);
            CEP(0,2,d); CEP(1,3,d); CEP(4,6,d); CEP(5,7,d);
            CEP(0,1,d); CEP(2,3,d); CEP(4,5,d); CEP(6,7,d);
        }
        // k = 16..256: cross-lane shfl steps then in-register tail
        #pragma unroll
        for (int kk = 16; kk <= 256; kk <<= 1) {
            const bool desc = ((lane & (kk >> 3)) == 0);
            #pragma unroll
            for (int j = kk >> 1; j >= 8; j >>= 1) {
                const int  jl = j >> 3;
                const bool i_lower = ((lane & jl) == 0);
                #pragma unroll
                for (int i = 0; i < 8; i++) {
                    float ok = __shfl_xor_sync(0xffffffffu, kt[i], jl);
                    float oe = __shfl_xor_sync(0xffffffffu, ke[i], jl);
                    bool my_g = (kt[i] > ok) || ((kt[i] == ok) && i_lower);
                    if (my_g != (i_lower == desc)) { kt[i] = ok; ke[i] = oe; }
                }
            }
            CEP(0,4,desc); CEP(1,5,desc); CEP(2,6,desc); CEP(3,7,desc);
            CEP(0,2,desc); CEP(1,3,desc); CEP(4,6,desc); CEP(5,7,desc);
            CEP(0,1,desc); CEP(2,3,desc); CEP(4,5,desc); CEP(6,7,desc);
        }

        // inclusive prefix sum of sorted e
        #pragma unroll
        for (int i = 1; i < 8; i++) ke[i] += ke[i - 1];
        float run = ke[7];
        #pragma unroll
        for (int off = 1; off < 32; off <<= 1) {
            float n = __shfl_up_sync(0xffffffffu, run, off);
            if (lane >= off) run += n;
        }
        float excl = __shfl_up_sync(0xffffffffu, run, 1);
        if (lane == 0) excl = 0.f;
        #pragma unroll
        for (int i = 0; i < 8; i++) ke[i] += excl;

        // publish chunk (coalesced float4 stores)
        float* gt = g_tsrt + blk * RPB + lane * 8;
        float* gp = g_pe   + blk * RPB + lane * 8;
        ((float4*)gt)[0] = make_float4(kt[0], kt[1], kt[2], kt[3]);
        ((float4*)gt)[1] = make_float4(kt[4], kt[5], kt[6], kt[7]);
        ((float4*)gp)[0] = make_float4(ke[0], ke[1], ke[2], ke[3]);
        ((float4*)gp)[1] = make_float4(ke[4], ke[5], ke[6], ke[7]);
    }

    grid_bar();    // single global sync: all chunks published

    // ================= Phase C: all 1024 threads, 4 per row =================
    #pragma unroll
    for (int i = tid; i < NB; i += NT)
        t_tab[(i >> 8) * TPAD + (i & 255)] = __ldcg(&g_tsrt[i]);
    __syncthreads();

    const int q   = tid >> 2;       // local row (original order)
    const int sub = tid & 3;
    const float ti = st[q];

    int cw[8];
    #pragma unroll
    for (int k = 0; k < 8; k++) cw[k] = 0;
    #pragma unroll
    for (int s = CHK / 2; s > 0; s >>= 1) {
        #pragma unroll
        for (int k = 0; k < 8; k++)
            cw[k] += (t_tab[(sub * 8 + k) * TPAD + cw[k] + s - 1] > ti) ? s : 0;
    }
    #pragma unroll
    for (int k = 0; k < 8; k++)
        cw[k] += (t_tab[(sub * 8 + k) * TPAD + cw[k]] > ti) ? 1 : 0;

    float sum = 0.f;
    int   cnt = 0;
    #pragma unroll
    for (int k = 0; k < 8; k++) {
        if (cw[k] > 0) {
            sum += __ldcg(&g_pe[(sub * 8 + k) * CHK + cw[k] - 1]);
            cnt += cw[k];
        }
    }
    sum += __shfl_xor_sync(0xffffffffu, sum, 1);
    sum += __shfl_xor_sync(0xffffffffu, sum, 2);
    cnt += __shfl_xor_sync(0xffffffffu, cnt, 1);
    cnt += __shfl_xor_sync(0xffffffffu, cnt, 2);

    float per = 0.f;
    int   cv  = 0;
    if (sub == 0) {
        if ((sc[q] == 0) && (cnt > 0)) {
            per = __logf(sum) - srisk[q];
            cv  = 1;
        }
    }

    #pragma unroll
    for (int off = 16; off > 0; off >>= 1) {
        per += __shfl_xor_sync(0xffffffffu, per, off);
        cv  += __shfl_xor_sync(0xffffffffu, cv, off);
    }
    if (lane == 0) { bredf[wid] = per; bredi[wid] = cv; }
    __syncthreads();
    if (wid == 0) {
        float p2 = bredf[lane];
        int   c2 = bredi[lane];
        #pragma unroll
        for (int off = 16; off > 0; off >>= 1) {
            p2 += __shfl_xor_sync(0xffffffffu, p2, off);
            c2 += __shfl_xor_sync(0xffffffffu, c2, off);
        }
        if (lane == 0) {
            g_per[blk] = p2;
            g_cnt[blk] = c2;
            __threadfence();
            int tk = atomicAdd(&g_ticket, 1);
            is_last = (tk == GRID - 1) ? 1 : 0;
        }
    }
    __syncthreads();

    if (is_last && tid == 0) {
        __threadfence();
        float per_t = 0.f, nll_t = 0.f;
        int cnt_t = 0;
        #pragma unroll
        for (int b = 0; b < GRID; b++) {
            per_t += __ldcg(&g_per[b]);
            cnt_t += __ldcg(&g_cnt[b]);
            nll_t += __ldcg(&g_nll[b]);
        }
        float rank = (cnt_t > 0) ? (per_t / (float)cnt_t) : 0.f;
        out[0] = nll_t / (float)NB + 0.5f * rank;
        g_ticket = 0;   // self-reset for graph replay
    }
}

extern "C" void kernel_launch(void* const* d_in, const int* in_sizes, int n_in,
                              void* d_out, int out_size)
{
    const float* outputs = (const float*)d_in[0];
    const int*   y       = (const int*)d_in[1];
    const float* t       = (const float*)d_in[2];
    const int*   c       = (const int*)d_in[3];
    float*       out     = (float*)d_out;

    surv_one_kernel<<<GRID, NT>>>(outputs, y, t, c, out);
}

// round 10
// speedup vs baseline: 2.3949x; 2.3949x over previous
#include <cuda_runtime.h>
#include <math.h>

#define NB    8192
#define GRID  32
#define NT    1024
#define RPB   256          // rows per block = chunk size
#define CHK   256
#define TPAD  257          // padded chunk stride in smem floats

__device__ __align__(16) float g_tsrt[NB];
__device__ __align__(16) float g_pe[NB];
__device__ float g_nll[GRID];
__device__ float g_per[GRID];
__device__ int   g_cnt[GRID];
__device__ int   g_ticket;
__device__ unsigned g_bcount;
__device__ volatile unsigned g_bgen;

#define BAR256() asm volatile("bar.sync 1, 256;" ::: "memory")

__device__ __forceinline__ void grid_bar() {
    __threadfence();            // release: this thread's writes visible device-wide
    __syncthreads();
    if (threadIdx.x == 0) {
        unsigned gen = g_bgen;
        if (atomicAdd(&g_bcount, 1u) == GRID - 1) {
            g_bcount = 0;
            __threadfence();
            g_bgen = gen + 1;
        } else {
            while (g_bgen == gen) { __nanosleep(32); }
        }
        __threadfence();        // acquire
    }
    __syncthreads();
}

extern "C" __global__ void __launch_bounds__(NT, 1)
surv_one_kernel(const float* __restrict__ outputs,
                const int* __restrict__ y,
                const float* __restrict__ t,
                const int* __restrict__ c,
                float* __restrict__ out)
{
    __shared__ __align__(16) char sbuf[38016];
    float* se    = (float*)(sbuf);            // [256] e per local row
    float* srisk = (float*)(sbuf + 1024);     // [256]
    int*   sc    = (int*)  (sbuf + 2048);     // [256]
    int*   sidx  = (int*)  (sbuf + 3072);     // [256] sorted-pos -> local row
    float* st_s  = (float*)(sbuf + 4096);     // [256] sorted t
    // phase-B sort ping-pong buffers (overlap t_tab; B finishes before C)
    float* kbuf0 = (float*)(sbuf + 5120);
    int*   ibuf0 = (int*)  (sbuf + 6144);
    float* kbuf1 = (float*)(sbuf + 7168);
    int*   ibuf1 = (int*)  (sbuf + 8192);
    // phase-C global t table, padded stride
    float* t_tab = (float*)(sbuf + 5120);     // [32 * 257]
    __shared__ float wpart[8];
    __shared__ float bredf[32];
    __shared__ int   bredi[32];
    __shared__ int   is_last;

    const int tid  = threadIdx.x;
    const int blk  = blockIdx.x;
    const int lane = tid & 31;
    const int wid  = tid >> 5;

    // ================= Phase A + B: first 8 warps only =================
    if (tid < RPB) {
        const int r = blk * RPB + tid;

        // ---- collapsed row math (exact rewrite of reference NLL/risk) ----
        float4 o4 = ((const float4*)outputs)[r];
        float a0 = __expf(o4.x), a1 = __expf(o4.y);
        float a2 = __expf(o4.z), a3 = __expf(o4.w);
        // suffix products of (1+a_k) for Sum(S_k) = Q / P3
        float v3   = 1.f + a3;
        float v23  = (1.f + a2) * v3;
        float v123 = (1.f + a1) * v23;
        float Q    = v123 + v23 + v3 + 1.f;
        // prefix products P_y = prod_{j<=y}(1+a_j)
        float h0 = 1.f + a0;
        float h1 = h0 * (1.f + a1);
        float h2 = h1 * (1.f + a2);
        float h3 = h0 * v123;
        float risk = -__fdividef(Q, h3);

        int yi = y[r];
        float Py = (yi == 0) ? h0 : (yi == 1) ? h1 : (yi == 2) ? h2 : h3;
        float oy = (yi == 0) ? o4.x : (yi == 1) ? o4.y : (yi == 2) ? o4.z : o4.w;
        float cf = (float)c[r];
        float nll = __logf(Py) - (1.f - cf) * oy;

        se[tid]    = __expf(risk);
        srisk[tid] = risk;
        sc[tid]    = c[r];

        // NLL reduction over 8 warps
        #pragma unroll
        for (int off = 16; off > 0; off >>= 1)
            nll += __shfl_xor_sync(0xffffffffu, nll, off);
        if (lane == 0) wpart[wid] = nll;
        BAR256();
        if (tid == 0) {
            float s = 0.f;
            #pragma unroll
            for (int w = 0; w < 8; w++) s += wpart[w];
            g_nll[blk] = s;
        }

        // ---- bitonic sort of 256 (key t desc, payload local idx) ----
        float kt = t[r];
        int   idx = tid;
        int buf = 0;
        for (int k = 2; k <= RPB; k <<= 1) {
            const bool desc = ((tid & k) == 0);
            int j = k >> 1;
            for (; j >= 32; j >>= 1) {           // cross-warp: ping-pong smem
                float* K = buf ? kbuf1 : kbuf0;
                int*   I = buf ? ibuf1 : ibuf0;
                K[tid] = kt; I[tid] = idx;
                BAR256();
                int p = tid ^ j;
                float ok = K[p]; int oi = I[p];
                bool i_lower = ((tid & j) == 0);
                bool my_g = (kt > ok) || ((kt == ok) && (idx < oi));
                if (my_g != (i_lower == desc)) { kt = ok; idx = oi; }
                buf ^= 1;
            }
            for (; j > 0; j >>= 1) {             // intra-warp: shfl
                float ok = __shfl_xor_sync(0xffffffffu, kt, j);
                int   oi = __shfl_xor_sync(0xffffffffu, idx, j);
                bool i_lower = ((tid & j) == 0);
                bool my_g = (kt > ok) || ((kt == ok) && (idx < oi));
                if (my_g != (i_lower == desc)) { kt = ok; idx = oi; }
            }
        }
        BAR256();                 // sort exchanges done before se gather / wpart reuse

        st_s[tid] = kt;
        sidx[tid] = idx;

        // inclusive prefix sum of sorted e
        float v = se[idx];
        float x = v;
        #pragma unroll
        for (int off = 1; off < 32; off <<= 1) {
            float n = __shfl_up_sync(0xffffffffu, x, off);
            if (lane >= off) x += n;
        }
        if (lane == 31) wpart[wid] = x;
        BAR256();
        float woff = 0.f;
        for (int w = 0; w < wid; w++) woff += wpart[w];
        float pref = x + woff;

        g_tsrt[blk * RPB + tid] = kt;
        g_pe[blk * RPB + tid]   = pref;
    }

    grid_bar();    // single global sync: all chunks published

    // ================= Phase C: all 1024 threads =================
    // L2-coherent loads (__ldcg): g_tsrt/g_pe were written THIS kernel.
    #pragma unroll
    for (int i = tid; i < NB; i += NT)
        t_tab[(i >> 8) * TPAD + (i & 255)] = __ldcg(&g_tsrt[i]);
    __syncthreads();

    const int q   = tid >> 2;       // sorted position within block's chunk
    const int sub = tid & 3;
    const float ti = st_s[q];

    int cw[8];
    #pragma unroll
    for (int k = 0; k < 8; k++) cw[k] = 0;
    #pragma unroll
    for (int s = CHK / 2; s > 0; s >>= 1) {
        #pragma unroll
        for (int k = 0; k < 8; k++)
            cw[k] += (t_tab[(sub * 8 + k) * TPAD + cw[k] + s - 1] > ti) ? s : 0;
    }
    #pragma unroll
    for (int k = 0; k < 8; k++)
        cw[k] += (t_tab[(sub * 8 + k) * TPAD + cw[k]] > ti) ? 1 : 0;

    float sum = 0.f;
    int   cnt = 0;
    #pragma unroll
    for (int k = 0; k < 8; k++) {
        if (cw[k] > 0) {
            sum += __ldcg(&g_pe[(sub * 8 + k) * CHK + cw[k] - 1]);
            cnt += cw[k];
        }
    }
    sum += __shfl_xor_sync(0xffffffffu, sum, 1);
    sum += __shfl_xor_sync(0xffffffffu, sum, 2);
    cnt += __shfl_xor_sync(0xffffffffu, cnt, 1);
    cnt += __shfl_xor_sync(0xffffffffu, cnt, 2);

    float per = 0.f;
    int   cv  = 0;
    if (sub == 0) {
        int id = sidx[q];
        if ((sc[id] == 0) && (cnt > 0)) {
            per = __logf(sum) - srisk[id];
            cv  = 1;
        }
    }

    #pragma unroll
    for (int off = 16; off > 0; off >>= 1) {
        per += __shfl_xor_sync(0xffffffffu, per, off);
        cv  += __shfl_xor_sync(0xffffffffu, cv, off);
    }
    if (lane == 0) { bredf[wid] = per; bredi[wid] = cv; }
    __syncthreads();
    if (wid == 0) {
        float p2 = bredf[lane];
        int   c2 = bredi[lane];
        #pragma unroll
        for (int off = 16; off > 0; off >>= 1) {
            p2 += __shfl_xor_sync(0xffffffffu, p2, off);
            c2 += __shfl_xor_sync(0xffffffffu, c2, off);
        }
        if (lane == 0) {
            g_per[blk] = p2;
            g_cnt[blk] = c2;
            __threadfence();
            int tk = atomicAdd(&g_ticket, 1);
            is_last = (tk == GRID - 1) ? 1 : 0;
        }
    }
    __syncthreads();

    if (is_last && tid == 0) {
        __threadfence();      // acquire before reading other blocks' partials
        float per_t = 0.f, nll_t = 0.f;
        int cnt_t = 0;
        #pragma unroll
        for (int b = 0; b < GRID; b++) {
            per_t += __ldcg(&g_per[b]);
            cnt_t += __ldcg(&g_cnt[b]);
            nll_t += __ldcg(&g_nll[b]);
        }
        float rank = (cnt_t > 0) ? (per_t / (float)cnt_t) : 0.f;
        out[0] = nll_t / (float)NB + 0.5f * rank;
        g_ticket = 0;     // self-reset for graph replay
    }
}

extern "C" void kernel_launch(void* const* d_in, const int* in_sizes, int n_in,
                              void* d_out, int out_size)
{
    const float* outputs = (const float*)d_in[0];
    const int*   y       = (const int*)d_in[1];
    const float* t       = (const float*)d_in[2];
    const int*   c       = (const int*)d_in[3];
    float*       out     = (float*)d_out;

    surv_one_kernel<<<GRID, NT>>>(outputs, y, t, c, out);
}